// round 6
// baseline (speedup 1.0000x reference)
#include <cuda_runtime.h>

#define DFEAT 48
#define NCG   12                       // float4 column-groups per row (48/4)
#define CHUNK 512                      // edges per block in k_main
#define NWALK 32                       // row-walkers per column-group
#define WALKR (CHUNK / NWALK)          // 16 rows per walker
#define MAIN_THREADS (NCG * NWALK)     // 384

// Per-node softmax denominators (N = 50000 here; padded)
__device__ float g_denom[65536];

// Edge-parallel denom accumulation: each thread takes 4 consecutive edges
// (float4/int4 loads), aggregates same-sid runs locally, flushes boundaries.
__global__ void k_exp(const float* __restrict__ a,
                      const int* __restrict__ seg, int E) {
    int t = blockIdx.x * blockDim.x + threadIdx.x;
    int e0 = t * 4;
    if (e0 >= E) return;

    if (e0 + 4 <= E) {
        float4 av = *(const float4*)(a + e0);
        int4   sv = *(const int4*)(seg + e0);
        float acc = __expf(av.x);
        int   cur = sv.x;
        if (sv.y != cur) { atomicAdd(&g_denom[cur], acc); acc = 0.0f; cur = sv.y; }
        acc += __expf(av.y);
        if (sv.z != cur) { atomicAdd(&g_denom[cur], acc); acc = 0.0f; cur = sv.z; }
        acc += __expf(av.z);
        if (sv.w != cur) { atomicAdd(&g_denom[cur], acc); acc = 0.0f; cur = sv.w; }
        acc += __expf(av.w);
        atomicAdd(&g_denom[cur], acc);
    } else {
        for (int e = e0; e < E; e++)
            atomicAdd(&g_denom[seg[e]], __expf(a[e]));
    }
}

__device__ __forceinline__ void flush4(float* __restrict__ out,
                                       int node, int cg, float4 acc) {
    float* p = out + (size_t)node * DFEAT + cg * 4;
    atomicAdd(p + 0, acc.x);
    atomicAdd(p + 1, acc.y);
    atomicAdd(p + 2, acc.z);
    atomicAdd(p + 3, acc.w);
}

// Main pass: block = 512 contiguous edges. 12 float4-column-groups x 32
// row-walkers; each walker sweeps 16 consecutive rows in batches of 4
// (4 independent LDG.128 in flight) with a running float4 segment
// accumulator; flushes via atomicAdd only at segment boundaries.
__global__ void __launch_bounds__(MAIN_THREADS, 4)
k_main(const float* __restrict__ a,
       const float* __restrict__ ft,
       const int* __restrict__ seg,
       float* __restrict__ out, int E) {
    __shared__ float w_s[CHUNK];
    __shared__ int   s_s[CHUNK];

    int base = blockIdx.x * CHUNK;
    int tid  = threadIdx.x;

    // Stage: per-edge softmax weights (one EX2 + one fast-div per edge)
    for (int i = tid; i < CHUNK; i += MAIN_THREADS) {
        int e = base + i;
        if (e < E) {
            int sid = seg[e];
            w_s[i] = __fdividef(__expf(a[e]), g_denom[sid]);
            s_s[i] = sid;
        } else {
            w_s[i] = 0.0f;
            s_s[i] = -1;
        }
    }
    __syncthreads();

    int cg = tid % NCG;            // float4 column group (0..11)
    int y  = tid / NCG;            // walker id (0..31)
    int j0 = y * WALKR;

    const float4* ft4 = (const float4*)ft;

    int    cur = s_s[j0];
    float4 acc = make_float4(0.f, 0.f, 0.f, 0.f);

    if (base + CHUNK <= E) {
        // fast path: all rows valid; batch 4 rows per step for MLP
        #pragma unroll
        for (int kb = 0; kb < WALKR; kb += 4) {
            int j = j0 + kb;
            size_t r = (size_t)(base + j) * NCG + cg;
            float4 v0 = ft4[r];
            float4 v1 = ft4[r + NCG];
            float4 v2 = ft4[r + 2 * NCG];
            float4 v3 = ft4[r + 3 * NCG];
            float w0 = w_s[j];     int sd0 = s_s[j];
            float w1 = w_s[j + 1]; int sd1 = s_s[j + 1];
            float w2 = w_s[j + 2]; int sd2 = s_s[j + 2];
            float w3 = w_s[j + 3]; int sd3 = s_s[j + 3];

            if (sd0 != cur) { flush4(out, cur, cg, acc); acc = make_float4(0.f,0.f,0.f,0.f); cur = sd0; }
            acc.x += w0 * v0.x; acc.y += w0 * v0.y; acc.z += w0 * v0.z; acc.w += w0 * v0.w;
            if (sd1 != cur) { flush4(out, cur, cg, acc); acc = make_float4(0.f,0.f,0.f,0.f); cur = sd1; }
            acc.x += w1 * v1.x; acc.y += w1 * v1.y; acc.z += w1 * v1.z; acc.w += w1 * v1.w;
            if (sd2 != cur) { flush4(out, cur, cg, acc); acc = make_float4(0.f,0.f,0.f,0.f); cur = sd2; }
            acc.x += w2 * v2.x; acc.y += w2 * v2.y; acc.z += w2 * v2.z; acc.w += w2 * v2.w;
            if (sd3 != cur) { flush4(out, cur, cg, acc); acc = make_float4(0.f,0.f,0.f,0.f); cur = sd3; }
            acc.x += w3 * v3.x; acc.y += w3 * v3.y; acc.z += w3 * v3.z; acc.w += w3 * v3.w;
        }
        flush4(out, cur, cg, acc);
    } else {
        for (int k = 0; k < WALKR; k++) {
            int j = j0 + k;
            int row = base + j;
            int   sid = s_s[j];
            float w   = w_s[j];
            float4 v = (row < E) ? ft4[(size_t)row * NCG + cg]
                                 : make_float4(0.f, 0.f, 0.f, 0.f);
            if (sid != cur) {
                if (cur >= 0) flush4(out, cur, cg, acc);
                acc = make_float4(0.f, 0.f, 0.f, 0.f);
                cur = sid;
            }
            acc.x += w * v.x;
            acc.y += w * v.y;
            acc.z += w * v.z;
            acc.w += w * v.w;
        }
        if (cur >= 0) flush4(out, cur, cg, acc);
    }
}

extern "C" void kernel_launch(void* const* d_in, const int* in_sizes, int n_in,
                              void* d_out, int out_size) {
    const float* a   = (const float*)d_in[0];
    const float* ft  = (const float*)d_in[1];
    const int*   seg = (const int*)d_in[2];
    float* out = (float*)d_out;

    int E = in_sizes[0];

    // Output accumulated via atomics -> zero it (harness poisons to 0xAA).
    cudaMemsetAsync(out, 0, (size_t)out_size * sizeof(float));

    // Zero denominators directly on the device symbol (no kernel launch).
    void* denom_ptr = nullptr;
    cudaGetSymbolAddress(&denom_ptr, g_denom);
    cudaMemsetAsync(denom_ptr, 0, sizeof(g_denom));

    int e4 = (E + 3) / 4;
    k_exp<<<(e4 + 255) / 256, 256>>>(a, seg, E);

    int mb = (E + CHUNK - 1) / CHUNK;
    k_main<<<mb, MAIN_THREADS>>>(a, ft, seg, out, E);
}

// round 7
// speedup vs baseline: 1.0972x; 1.0972x over previous
#include <cuda_runtime.h>
#include <cstdint>

#define DFEAT 48
#define NCG   12                       // float4 column-groups per row (48/4)
#define CHUNK 512                      // edges per block in k_main
#define NWALK 32                       // row-walkers per column-group
#define WALKR (CHUNK / NWALK)          // 16 rows per walker
#define MAIN_THREADS (NCG * NWALK)     // 384

#define FT_TILE_BYTES (CHUNK * DFEAT * 4)          // 98304 (96KB)
#define SMEM_W_OFF    FT_TILE_BYTES                // w_s: CHUNK floats
#define SMEM_S_OFF    (FT_TILE_BYTES + CHUNK * 4)  // s_s: CHUNK ints
#define SMEM_MBAR_OFF (FT_TILE_BYTES + CHUNK * 8)  // mbarrier (8B)
#define SMEM_TOTAL    (SMEM_MBAR_OFF + 16)

// Per-node softmax denominators (N = 50000 here; padded)
__device__ float g_denom[65536];

// Edge-parallel denom accumulation: each thread takes 4 consecutive edges
// (float4/int4 loads), aggregates same-sid runs locally, flushes boundaries.
__global__ void k_exp(const float* __restrict__ a,
                      const int* __restrict__ seg, int E) {
    int t = blockIdx.x * blockDim.x + threadIdx.x;
    int e0 = t * 4;
    if (e0 >= E) return;

    if (e0 + 4 <= E) {
        float4 av = *(const float4*)(a + e0);
        int4   sv = *(const int4*)(seg + e0);
        float acc = __expf(av.x);
        int   cur = sv.x;
        if (sv.y != cur) { atomicAdd(&g_denom[cur], acc); acc = 0.0f; cur = sv.y; }
        acc += __expf(av.y);
        if (sv.z != cur) { atomicAdd(&g_denom[cur], acc); acc = 0.0f; cur = sv.z; }
        acc += __expf(av.z);
        if (sv.w != cur) { atomicAdd(&g_denom[cur], acc); acc = 0.0f; cur = sv.w; }
        acc += __expf(av.w);
        atomicAdd(&g_denom[cur], acc);
    } else {
        for (int e = e0; e < E; e++)
            atomicAdd(&g_denom[seg[e]], __expf(a[e]));
    }
}

__device__ __forceinline__ uint32_t smem_u32(const void* p) {
    return (uint32_t)__cvta_generic_to_shared(p);
}

__device__ __forceinline__ void mbar_init(uint32_t mbar, uint32_t count) {
    asm volatile("mbarrier.init.shared.b64 [%0], %1;" :: "r"(mbar), "r"(count) : "memory");
}
__device__ __forceinline__ void mbar_expect_tx(uint32_t mbar, uint32_t bytes) {
    asm volatile("mbarrier.arrive.expect_tx.shared.b64 _, [%0], %1;"
                 :: "r"(mbar), "r"(bytes) : "memory");
}
__device__ __forceinline__ void bulk_g2s(uint32_t dst_smem, const void* src_gmem,
                                         uint32_t bytes, uint32_t mbar) {
    asm volatile(
        "cp.async.bulk.shared::cta.global.mbarrier::complete_tx::bytes "
        "[%0], [%1], %2, [%3];"
        :: "r"(dst_smem), "l"(src_gmem), "r"(bytes), "r"(mbar) : "memory");
}
__device__ __forceinline__ void mbar_wait(uint32_t mbar, uint32_t parity) {
    asm volatile(
        "{\n\t"
        ".reg .pred P;\n\t"
        "W%=:\n\t"
        "mbarrier.try_wait.parity.shared::cta.b64 P, [%0], %1;\n\t"
        "@!P bra W%=;\n\t"
        "}"
        :: "r"(mbar), "r"(parity) : "memory");
}

__device__ __forceinline__ void flush4(float* __restrict__ out,
                                       int node, int cg, float4 acc) {
    float* p = out + (size_t)node * DFEAT + cg * 4;
    atomicAdd(p + 0, acc.x);
    atomicAdd(p + 1, acc.y);
    atomicAdd(p + 2, acc.z);
    atomicAdd(p + 3, acc.w);
}

// Main pass: block = 512 contiguous edges. One TMA bulk copy stages the whole
// 96KB ft chunk into smem (no register-dependent loads); weight staging
// overlaps the copy. Then 12 float4-column-groups x 32 row-walkers accumulate
// from smem; flush via atomicAdd only at segment boundaries (seg is sorted).
__global__ void __launch_bounds__(MAIN_THREADS, 2)
k_main(const float* __restrict__ a,
       const float* __restrict__ ft,
       const int* __restrict__ seg,
       float* __restrict__ out, int E) {
    extern __shared__ __align__(128) char smem[];
    float4* s_ft = (float4*)smem;
    float*  w_s  = (float*)(smem + SMEM_W_OFF);
    int*    s_s  = (int*)(smem + SMEM_S_OFF);
    uint32_t mbar = smem_u32(smem + SMEM_MBAR_OFF);

    int base = blockIdx.x * CHUNK;
    int tid  = threadIdx.x;
    bool full = (base + CHUNK <= E);

    if (tid == 0) mbar_init(mbar, 1);
    __syncthreads();

    if (full && tid == 0) {
        mbar_expect_tx(mbar, FT_TILE_BYTES);
        bulk_g2s(smem_u32(s_ft), ft + (size_t)base * DFEAT, FT_TILE_BYTES, mbar);
    }

    // Stage per-edge softmax weights (overlaps the TMA copy)
    for (int i = tid; i < CHUNK; i += MAIN_THREADS) {
        int e = base + i;
        if (e < E) {
            int sid = seg[e];
            w_s[i] = __fdividef(__expf(a[e]), g_denom[sid]);
            s_s[i] = sid;
        } else {
            w_s[i] = 0.0f;
            s_s[i] = -1;
        }
    }

    if (!full) {
        // Tail chunk: guarded per-thread loads into smem
        const float4* ft4 = (const float4*)ft;
        for (int i = tid; i < CHUNK * NCG; i += MAIN_THREADS) {
            int row = base + i / NCG;
            s_ft[i] = (row < E) ? ft4[(size_t)row * NCG + (i % NCG)]
                                : make_float4(0.f, 0.f, 0.f, 0.f);
        }
    }
    __syncthreads();
    if (full) mbar_wait(mbar, 0);

    int cg = tid % NCG;            // float4 column group (0..11)
    int y  = tid / NCG;            // walker id (0..31)
    int j0 = y * WALKR;

    int    cur = s_s[j0];
    float4 acc = make_float4(0.f, 0.f, 0.f, 0.f);

    #pragma unroll
    for (int k = 0; k < WALKR; k++) {
        int j = j0 + k;
        int    sid = s_s[j];
        float  w   = w_s[j];
        float4 v   = s_ft[j * NCG + cg];
        if (sid != cur) {
            if (cur >= 0) flush4(out, cur, cg, acc);
            acc = make_float4(0.f, 0.f, 0.f, 0.f);
            cur = sid;
        }
        acc.x += w * v.x;
        acc.y += w * v.y;
        acc.z += w * v.z;
        acc.w += w * v.w;
    }
    if (cur >= 0) flush4(out, cur, cg, acc);
}

extern "C" void kernel_launch(void* const* d_in, const int* in_sizes, int n_in,
                              void* d_out, int out_size) {
    const float* a   = (const float*)d_in[0];
    const float* ft  = (const float*)d_in[1];
    const int*   seg = (const int*)d_in[2];
    float* out = (float*)d_out;

    int E = in_sizes[0];

    // Output accumulated via atomics -> zero it (harness poisons to 0xAA).
    cudaMemsetAsync(out, 0, (size_t)out_size * sizeof(float));

    // Zero denominators directly on the device symbol (no kernel launch).
    void* denom_ptr = nullptr;
    cudaGetSymbolAddress(&denom_ptr, g_denom);
    cudaMemsetAsync(denom_ptr, 0, sizeof(g_denom));

    int e4 = (E + 3) / 4;
    k_exp<<<(e4 + 255) / 256, 256>>>(a, seg, E);

    cudaFuncSetAttribute(k_main, cudaFuncAttributeMaxDynamicSharedMemorySize,
                         SMEM_TOTAL);
    int mb = (E + CHUNK - 1) / CHUNK;
    k_main<<<mb, MAIN_THREADS, SMEM_TOTAL>>>(a, ft, seg, out, E);
}